// round 11
// baseline (speedup 1.0000x reference)
#include <cuda_runtime.h>
#include <cstdint>

// DIoU loss, HBM-bound streaming reduction (144 MB read, scalar out).
// R11: cp.async.bulk (UBLKCP) 3-stage smem pipeline. Latency hiding moved
// from registers (two cliffs: <40 regs serializes loads, >42 breaks
// residency) to bulk-async copies: 3 x 36KB in flight per CTA, compute
// reads smem. 2 CTAs/SM (smem-limited), grid=296 fully resident,
// 4096 tiles / 296 = 13.84 -> 1.2% round-quantization tail (vs R8's 8%).

#define EPS 1e-7f
#define THREADS 256
#define TILE 1024
#define STAGES 3

// smem layout (dynamic): A[3]=16KB each, B[3]=16KB each, M[3]=4KB each, bars
#define SM_A(s) ((s) * 16384)
#define SM_B(s) (49152 + (s) * 16384)
#define SM_M(s) (98304 + (s) * 4096)
#define SM_BAR  110592
#define SMEM_TOTAL (110592 + 64)
#define STAGE_BYTES (16384 + 16384 + 4096)

#define MAX_BLOCKS 2048

__device__ float g_partials[MAX_BLOCKS];
__device__ unsigned int g_ticket = 0;

__device__ __forceinline__ float diou_loss(float4 a, float4 b) {
    float area1 = (a.z - a.x) * (a.w - a.y);
    float area2 = (b.z - b.x) * (b.w - b.y);

    float ltx = fmaxf(a.x, b.x);
    float lty = fmaxf(a.y, b.y);
    float rbx = fminf(a.z, b.z);
    float rby = fminf(a.w, b.w);
    float iw = fmaxf(rbx - ltx, 0.0f);
    float ih = fmaxf(rby - lty, 0.0f);
    float inter = iw * ih;
    float uni = area1 + area2 - inter;

    float cltx = fminf(a.x, b.x);
    float clty = fminf(a.y, b.y);
    float crbx = fmaxf(a.z, b.z);
    float crby = fmaxf(a.w, b.w);
    float wc = crbx - cltx;
    float hc = crby - clty;
    float area_c = wc * hc;

    float iou = __fdividef(inter, uni);
    float giou = iou - __fdividef(area_c - uni, area_c);

    float dcx = (a.x + a.z) * 0.5f - (b.x + b.z) * 0.5f;
    float dcy = (a.y + a.w) * 0.5f - (b.y + b.w) * 0.5f;
    float d2 = dcx * dcx + dcy * dcy;
    float diag2 = wc * wc + hc * hc;
    float diou = giou - __fdividef(d2, diag2 + EPS);

    return 1.0f - diou;
}

__device__ __forceinline__ uint32_t smem_u32(const void* p) {
    return (uint32_t)__cvta_generic_to_shared(p);
}
__device__ __forceinline__ void mbar_init(uint32_t mbar, uint32_t count) {
    asm volatile("mbarrier.init.shared.b64 [%0], %1;"
                 :: "r"(mbar), "r"(count) : "memory");
}
__device__ __forceinline__ void mbar_expect_tx(uint32_t mbar, uint32_t bytes) {
    asm volatile("mbarrier.arrive.expect_tx.shared.b64 _, [%0], %1;"
                 :: "r"(mbar), "r"(bytes) : "memory");
}
__device__ __forceinline__ void bulk_g2s(uint32_t dst, const void* src,
                                         uint32_t bytes, uint32_t mbar) {
    asm volatile(
        "cp.async.bulk.shared::cta.global.mbarrier::complete_tx::bytes "
        "[%0], [%1], %2, [%3];"
        :: "r"(dst), "l"(src), "r"(bytes), "r"(mbar) : "memory");
}
__device__ __forceinline__ void mbar_wait(uint32_t mbar, uint32_t parity) {
    asm volatile(
        "{\n\t"
        ".reg .pred P;\n\t"
        "W_%=:\n\t"
        "mbarrier.try_wait.parity.acquire.cta.shared::cta.b64 P, [%0], %1, 0x989680;\n\t"
        "@P bra D_%=;\n\t"
        "bra W_%=;\n\t"
        "D_%=:\n\t"
        "}"
        :: "r"(mbar), "r"(parity) : "memory");
}

__global__ void __launch_bounds__(THREADS)
diou_kernel(const float4* __restrict__ boxes1,
            const float4* __restrict__ boxes2,
            const int* __restrict__ mask,
            const int* __restrict__ num_boxes,
            float* __restrict__ out,
            int N, int numTiles) {
    extern __shared__ __align__(16) char smem[];
    uint32_t smem_base = smem_u32(smem);
    int tid = threadIdx.x;
    int bid = blockIdx.x;
    int grid = gridDim.x;

    // Balanced contiguous tile range per CTA.
    int tBeg = (int)(((long long)numTiles * bid) / grid);
    int tEnd = (int)(((long long)numTiles * (bid + 1)) / grid);
    int myTiles = tEnd - tBeg;

    uint32_t bar = smem_base + SM_BAR;
    if (tid == 0) {
        #pragma unroll
        for (int s = 0; s < STAGES; s++) mbar_init(bar + s * 8, 1);
        asm volatile("fence.proxy.async.shared::cta;" ::: "memory");
        // Prime the pipeline.
        int pre = myTiles < STAGES ? myTiles : STAGES;
        for (int s = 0; s < pre; s++) {
            int t = tBeg + s;
            uint32_t mb = bar + s * 8;
            mbar_expect_tx(mb, STAGE_BYTES);
            bulk_g2s(smem_base + SM_A(s), boxes1 + (size_t)t * TILE, 16384, mb);
            bulk_g2s(smem_base + SM_B(s), boxes2 + (size_t)t * TILE, 16384, mb);
            bulk_g2s(smem_base + SM_M(s), mask   + (size_t)t * TILE, 4096,  mb);
        }
    }
    __syncthreads();

    float acc = 0.0f;

    for (int k = 0; k < myTiles; k++) {
        int s = k % STAGES;
        uint32_t ph = (uint32_t)((k / STAGES) & 1);
        mbar_wait(bar + s * 8, ph);

        const float4* sa = (const float4*)(smem + SM_A(s));
        const float4* sb = (const float4*)(smem + SM_B(s));
        const int*    sm = (const int*)(smem + SM_M(s));
        #pragma unroll
        for (int j = 0; j < TILE / THREADS; j++) {
            int i = j * THREADS + tid;
            float4 a = sa[i];
            float4 b = sb[i];
            int m = sm[i];
            acc += diou_loss(a, b) * (float)(m != 0);
        }
        __syncthreads();  // all consumers done with stage s -> stage is empty

        int tn = tBeg + k + STAGES;
        if (tid == 0 && tn < tEnd) {
            uint32_t mb = bar + s * 8;
            mbar_expect_tx(mb, STAGE_BYTES);
            bulk_g2s(smem_base + SM_A(s), boxes1 + (size_t)tn * TILE, 16384, mb);
            bulk_g2s(smem_base + SM_B(s), boxes2 + (size_t)tn * TILE, 16384, mb);
            bulk_g2s(smem_base + SM_M(s), mask   + (size_t)tn * TILE, 4096,  mb);
        }
    }

    // Ragged tail beyond full tiles (none for N = 4096*1024, but be safe).
    if (bid == grid - 1) {
        for (int i = numTiles * TILE + tid; i < N; i += THREADS) {
            float4 a = __ldcs(&boxes1[i]);
            float4 b = __ldcs(&boxes2[i]);
            int m = __ldcs(&mask[i]);
            acc += diou_loss(a, b) * (float)(m != 0);
        }
    }

    // Block reduce.
    #pragma unroll
    for (int off = 16; off > 0; off >>= 1)
        acc += __shfl_down_sync(0xFFFFFFFFu, acc, off);

    __shared__ float warp_sums[THREADS / 32];
    __shared__ bool is_last;
    int lane = threadIdx.x & 31;
    int wid = threadIdx.x >> 5;
    if (lane == 0) warp_sums[wid] = acc;
    __syncthreads();

    if (wid == 0) {
        float v = (lane < THREADS / 32) ? warp_sums[lane] : 0.0f;
        #pragma unroll
        for (int off = 4; off > 0; off >>= 1)
            v += __shfl_down_sync(0xFFFFFFFFu, v, off);
        if (lane == 0) {
            g_partials[blockIdx.x] = v;
            __threadfence();
            unsigned int ticket = atomicAdd(&g_ticket, 1u);
            is_last = (ticket == gridDim.x - 1);
        }
    }
    __syncthreads();

    if (is_last) {
        float v = 0.0f;
        for (int i = threadIdx.x; i < gridDim.x; i += THREADS)
            v += g_partials[i];
        #pragma unroll
        for (int off = 16; off > 0; off >>= 1)
            v += __shfl_down_sync(0xFFFFFFFFu, v, off);
        if (lane == 0) warp_sums[wid] = v;
        __syncthreads();
        if (wid == 0) {
            float s = (lane < THREADS / 32) ? warp_sums[lane] : 0.0f;
            #pragma unroll
            for (int off = 4; off > 0; off >>= 1)
                s += __shfl_down_sync(0xFFFFFFFFu, s, off);
            if (lane == 0) {
                g_ticket = 0;
                out[0] = s * (1.0f / (float)num_boxes[0]);
            }
        }
    }
}

extern "C" void kernel_launch(void* const* d_in, const int* in_sizes, int n_in,
                              void* d_out, int out_size) {
    const float4* boxes1 = (const float4*)d_in[0];
    const float4* boxes2 = (const float4*)d_in[1];
    const int* mask = (const int*)d_in[2];
    const int* num_boxes = (const int*)d_in[3];
    float* out = (float*)d_out;

    int N = in_sizes[0] / 4;      // B*Q elements
    int numTiles = N / TILE;      // full tiles (4096)

    static bool attr_set = false;
    if (!attr_set) {
        cudaFuncSetAttribute(diou_kernel,
                             cudaFuncAttributeMaxDynamicSharedMemorySize,
                             SMEM_TOTAL);
        attr_set = true;
    }

    // 2 CTAs/SM (smem-limited: 110.7KB each), 148 SMs -> 296, one wave.
    int blocks = 296;
    if (blocks > numTiles && numTiles > 0) blocks = numTiles;
    if (blocks < 1) blocks = 1;

    diou_kernel<<<blocks, THREADS, SMEM_TOTAL>>>(boxes1, boxes2, mask,
                                                 num_boxes, out, N, numTiles);
}

// round 12
// speedup vs baseline: 1.3481x; 1.3481x over previous
#include <cuda_runtime.h>
#include <cstdint>

// DIoU loss, HBM-bound streaming reduction (144 MB read, scalar out).
// R12: R8 body (888 resident CTAs, front-batched 12 LDGs + L2 prefetch,
// single-launch finalize) with DYNAMIC tile scheduling via a global atomic
// ticket. Next ticket is acquired before computing the current tile, so
// the L2 prefetch of the next tile still overlaps compute. Removes R8's
// 8% round-quantization tail (544 CTAs x5 rounds vs 344 x4).

#define EPS 1e-7f
#define UNROLL 4
#define THREADS 256
#define TILE (THREADS * UNROLL)
#define MAX_BLOCKS 4096

__device__ float g_partials[MAX_BLOCKS];
__device__ unsigned int g_ticket = 0;   // finalize election
__device__ unsigned int g_work = 0;     // dynamic tile ticket

__device__ __forceinline__ float diou_loss(float4 a, float4 b) {
    float area1 = (a.z - a.x) * (a.w - a.y);
    float area2 = (b.z - b.x) * (b.w - b.y);

    float ltx = fmaxf(a.x, b.x);
    float lty = fmaxf(a.y, b.y);
    float rbx = fminf(a.z, b.z);
    float rby = fminf(a.w, b.w);
    float iw = fmaxf(rbx - ltx, 0.0f);
    float ih = fmaxf(rby - lty, 0.0f);
    float inter = iw * ih;
    float uni = area1 + area2 - inter;

    float cltx = fminf(a.x, b.x);
    float clty = fminf(a.y, b.y);
    float crbx = fmaxf(a.z, b.z);
    float crby = fmaxf(a.w, b.w);
    float wc = crbx - cltx;
    float hc = crby - clty;
    float area_c = wc * hc;

    float iou = __fdividef(inter, uni);
    float giou = iou - __fdividef(area_c - uni, area_c);

    float dcx = (a.x + a.z) * 0.5f - (b.x + b.z) * 0.5f;
    float dcy = (a.y + a.w) * 0.5f - (b.y + b.w) * 0.5f;
    float d2 = dcx * dcx + dcy * dcy;
    float diag2 = wc * wc + hc * hc;
    float diou = giou - __fdividef(d2, diag2 + EPS);

    return 1.0f - diou;
}

__device__ __forceinline__ void prefetch_l2(const void* p) {
    asm volatile("prefetch.global.L2 [%0];" :: "l"(p));
}

__global__ void __launch_bounds__(THREADS)
diou_kernel(const float4* __restrict__ boxes1,
            const float4* __restrict__ boxes2,
            const int* __restrict__ mask,
            const int* __restrict__ num_boxes,
            float* __restrict__ out,
            int N, int numTiles) {
    __shared__ int s_next;
    __shared__ float warp_sums[THREADS / 32];
    __shared__ bool is_last;

    int tid = threadIdx.x;
    int lane = tid & 31;
    int wid = tid >> 5;

    float acc = 0.0f;

    // Grab first tile.
    if (tid == 0) s_next = (int)atomicAdd(&g_work, 1u);
    __syncthreads();
    int t = s_next;

    while (t < numTiles) {
        // Acquire next ticket early (overlaps with this tile's loads).
        if (tid == 0) s_next = (int)atomicAdd(&g_work, 1u);

        int base = t * TILE + tid;
        // Front-batched unconditional loads: 12 LDGs in flight.
        float4 a[UNROLL], b[UNROLL];
        int m[UNROLL];
        #pragma unroll
        for (int j = 0; j < UNROLL; j++) {
            int i = base + j * THREADS;
            a[j] = __ldcs(&boxes1[i]);
            b[j] = __ldcs(&boxes2[i]);
            m[j] = __ldcs(&mask[i]);
        }

        __syncthreads();  // s_next visible to all threads
        int tn = s_next;

        // Prefetch next tile into L2 while this tile's loads are in flight.
        if (tn < numTiles) {
            int pb = tn * TILE + tid;
            #pragma unroll
            for (int j = 0; j < UNROLL; j++) {
                prefetch_l2(&boxes1[pb + j * THREADS]);
                prefetch_l2(&boxes2[pb + j * THREADS]);
                prefetch_l2(&mask[pb + j * THREADS]);
            }
        }

        #pragma unroll
        for (int j = 0; j < UNROLL; j++)
            acc += diou_loss(a[j], b[j]) * (float)(m[j] != 0);

        t = tn;
    }

    // Ragged tail beyond full tiles (none for N = 4096*1024; safety).
    if (blockIdx.x == 0) {
        for (int i = numTiles * TILE + tid; i < N; i += THREADS) {
            float4 a = __ldcs(&boxes1[i]);
            float4 b = __ldcs(&boxes2[i]);
            int m = __ldcs(&mask[i]);
            acc += diou_loss(a, b) * (float)(m != 0);
        }
    }

    // Block reduce.
    #pragma unroll
    for (int off = 16; off > 0; off >>= 1)
        acc += __shfl_down_sync(0xFFFFFFFFu, acc, off);

    if (lane == 0) warp_sums[wid] = acc;
    __syncthreads();

    if (wid == 0) {
        float v = (lane < THREADS / 32) ? warp_sums[lane] : 0.0f;
        #pragma unroll
        for (int off = 4; off > 0; off >>= 1)
            v += __shfl_down_sync(0xFFFFFFFFu, v, off);
        if (lane == 0) {
            g_partials[blockIdx.x] = v;
            __threadfence();
            unsigned int ticket = atomicAdd(&g_ticket, 1u);
            is_last = (ticket == gridDim.x - 1);
        }
    }
    __syncthreads();

    // Last block: reduce partials, write out, reset tickets for next replay.
    if (is_last) {
        float v = 0.0f;
        for (int i = threadIdx.x; i < gridDim.x; i += THREADS)
            v += g_partials[i];
        #pragma unroll
        for (int off = 16; off > 0; off >>= 1)
            v += __shfl_down_sync(0xFFFFFFFFu, v, off);
        if (lane == 0) warp_sums[wid] = v;
        __syncthreads();
        if (wid == 0) {
            float s = (lane < THREADS / 32) ? warp_sums[lane] : 0.0f;
            #pragma unroll
            for (int off = 4; off > 0; off >>= 1)
                s += __shfl_down_sync(0xFFFFFFFFu, s, off);
            if (lane == 0) {
                g_ticket = 0;
                g_work = 0;
                out[0] = s * (1.0f / (float)num_boxes[0]);
            }
        }
    }
}

extern "C" void kernel_launch(void* const* d_in, const int* in_sizes, int n_in,
                              void* d_out, int out_size) {
    const float4* boxes1 = (const float4*)d_in[0];
    const float4* boxes2 = (const float4*)d_in[1];
    const int* mask = (const int*)d_in[2];
    const int* num_boxes = (const int*)d_in[3];
    float* out = (float*)d_out;

    int N = in_sizes[0] / 4;   // B*Q elements
    int numTiles = N / TILE;   // 4096 full tiles

    // 888 = 148 SMs * 6 CTAs (40 regs) -> fully resident single wave.
    int blocks = 148 * 6;
    if (blocks > MAX_BLOCKS) blocks = MAX_BLOCKS;
    if (blocks < 1) blocks = 1;

    diou_kernel<<<blocks, THREADS>>>(boxes1, boxes2, mask, num_boxes, out,
                                     N, numTiles);
}